// round 4
// baseline (speedup 1.0000x reference)
#include <cuda_runtime.h>
#include <cstdint>

#define BB 2
#define LL 4096
#define DMODEL 512
#define NH 8
#define DHEAD 64

// Scratch (allocation-free rule: __device__ globals)
__device__ float g_Q[BB * NH * LL * DHEAD];
__device__ float g_K[BB * NH * LL * DHEAD];
__device__ float g_V[BB * NH * LL * DHEAD];   // stored TRANSPOSED: [B*H, d, L]
__device__ float g_O[BB * LL * DMODEL];

__device__ __forceinline__ uint32_t f2tf(float x) {
    uint32_t r;
    asm("cvt.rna.tf32.f32 %0, %1;" : "=r"(r) : "f"(x));
    return r;
}

// D += A(16x8) * B(8x8), tf32 inputs, fp32 accumulate
__device__ __forceinline__ void mma8(float* c, const uint32_t* a, const uint32_t* b) {
    asm volatile(
        "mma.sync.aligned.m16n8k8.row.col.f32.tf32.tf32.f32 "
        "{%0,%1,%2,%3}, {%4,%5,%6,%7}, {%8,%9}, {%0,%1,%2,%3};"
        : "+f"(c[0]), "+f"(c[1]), "+f"(c[2]), "+f"(c[3])
        : "r"(a[0]), "r"(a[1]), "r"(a[2]), "r"(a[3]), "r"(b[0]), "r"(b[1]));
}

// ---------------------------------------------------------------------------
// tf32 GEMM: C[M,N] = A[M,512] @ B[512,N], tile 128x128, 256 threads.
// mode 0: plain [M,512].  mode 1: head-split [B,H,L,64].
// mode 2: head-split TRANSPOSED [B,H,64,L] (for V).
// ---------------------------------------------------------------------------
#define GP_A 36
#define GP_B 136

__global__ __launch_bounds__(256, 2) void gemm_tf32(
    const float* __restrict__ A, const float* __restrict__ Bw,
    float* __restrict__ C, int mode)
{
    __shared__ uint32_t As[128 * GP_A];   // [m][k-chunk of 32], pad 36
    __shared__ uint32_t Bs[32 * GP_B];    // [k][n 128], pad 136

    const int tid = threadIdx.x;
    const int lane = tid & 31;
    const int wid = tid >> 5;
    const int g = lane >> 2, tig = lane & 3;
    const int wm = (wid & 3) * 32;
    const int wn = (wid >> 2) * 64;
    const int m0 = blockIdx.y * 128, n0 = blockIdx.x * 128;

    float acc[2][8][4];
    #pragma unroll
    for (int mt = 0; mt < 2; mt++)
        #pragma unroll
        for (int j = 0; j < 8; j++)
            #pragma unroll
            for (int r = 0; r < 4; r++) acc[mt][j][r] = 0.0f;

    for (int kt = 0; kt < DMODEL; kt += 32) {
        __syncthreads();
        #pragma unroll
        for (int i = 0; i < 4; i++) {
            int idx = tid + i * 256;
            int r = idx >> 3, c = (idx & 7) * 4;
            float4 v = *(const float4*)(A + (size_t)(m0 + r) * DMODEL + kt + c);
            uint32_t* p = &As[r * GP_A + c];
            p[0] = f2tf(v.x); p[1] = f2tf(v.y); p[2] = f2tf(v.z); p[3] = f2tf(v.w);
        }
        #pragma unroll
        for (int i = 0; i < 4; i++) {
            int idx = tid + i * 256;
            int r = idx >> 5, c = (idx & 31) * 4;
            float4 v = *(const float4*)(Bw + (size_t)(kt + r) * DMODEL + n0 + c);
            uint32_t* p = &Bs[r * GP_B + c];
            p[0] = f2tf(v.x); p[1] = f2tf(v.y); p[2] = f2tf(v.z); p[3] = f2tf(v.w);
        }
        __syncthreads();

        #pragma unroll
        for (int kk = 0; kk < 4; kk++) {
            uint32_t af[2][4], bf[8][2];
            #pragma unroll
            for (int mt = 0; mt < 2; mt++) {
                int r = wm + mt * 16;
                af[mt][0] = As[(r + g) * GP_A + kk * 8 + tig];
                af[mt][1] = As[(r + g + 8) * GP_A + kk * 8 + tig];
                af[mt][2] = As[(r + g) * GP_A + kk * 8 + tig + 4];
                af[mt][3] = As[(r + g + 8) * GP_A + kk * 8 + tig + 4];
            }
            #pragma unroll
            for (int j = 0; j < 8; j++) {
                bf[j][0] = Bs[(kk * 8 + tig) * GP_B + wn + j * 8 + g];
                bf[j][1] = Bs[(kk * 8 + tig + 4) * GP_B + wn + j * 8 + g];
            }
            #pragma unroll
            for (int mt = 0; mt < 2; mt++)
                #pragma unroll
                for (int j = 0; j < 8; j++)
                    mma8(acc[mt][j], af[mt], bf[j]);
        }
    }

    #pragma unroll
    for (int mt = 0; mt < 2; mt++) {
        int m_lo = m0 + wm + mt * 16 + g;
        int m_hi = m_lo + 8;
        #pragma unroll
        for (int j = 0; j < 8; j++) {
            int n = n0 + wn + j * 8 + 2 * tig;
            if (mode == 0) {
                *(float2*)&C[(size_t)m_lo * DMODEL + n] = make_float2(acc[mt][j][0], acc[mt][j][1]);
                *(float2*)&C[(size_t)m_hi * DMODEL + n] = make_float2(acc[mt][j][2], acc[mt][j][3]);
            } else {
                int h = n >> 6, d = n & 63;
                int b_lo = m_lo >> 12, l_lo = m_lo & (LL - 1);
                int b_hi = m_hi >> 12, l_hi = m_hi & (LL - 1);
                if (mode == 1) {
                    *(float2*)&C[(((size_t)(b_lo * NH + h)) * LL + l_lo) * DHEAD + d] =
                        make_float2(acc[mt][j][0], acc[mt][j][1]);
                    *(float2*)&C[(((size_t)(b_hi * NH + h)) * LL + l_hi) * DHEAD + d] =
                        make_float2(acc[mt][j][2], acc[mt][j][3]);
                } else {  // mode 2: transposed [B,H,d,L]
                    size_t blo = (size_t)(b_lo * NH + h) * DHEAD;
                    size_t bhi = (size_t)(b_hi * NH + h) * DHEAD;
                    C[(blo + d) * LL + l_lo]     = acc[mt][j][0];
                    C[(blo + d + 1) * LL + l_lo] = acc[mt][j][1];
                    C[(bhi + d) * LL + l_hi]     = acc[mt][j][2];
                    C[(bhi + d + 1) * LL + l_hi] = acc[mt][j][3];
                }
            }
        }
    }
}

// ---------------------------------------------------------------------------
// tf32 flash attention: grid (L/128, B*H), 256 threads (8 warps, 16 q each).
// K/V smem use pair-permuted columns so each MMA B-fragment is one LDS.64.
// Row stride 72 words -> conflict-free LDS.64 phases and staging STS.
// V comes from gmem already transposed [B,H,d,L].
// ---------------------------------------------------------------------------
#define KP2 72

__global__ __launch_bounds__(256) void attn_tf32(const int* __restrict__ mask)
{
    __shared__ uint32_t Ks[64 * KP2];   // K: row=key, paired cols over d
    __shared__ uint32_t Vt[64 * KP2];   // V^T: row=d, paired cols over key
    __shared__ float madd[64];

    const int tid = threadIdx.x;
    const int lane = tid & 31;
    const int wid = tid >> 5;           // 0..7
    const int g = lane >> 2, tig = lane & 3;
    const int bl = lane & 28;
    const int lo = tig >> 1, sel = tig & 1;

    const int q0 = blockIdx.x * 128;
    const int bh = blockIdx.y;
    const int b = bh >> 3, h = bh & 7;

    const float* Qg = g_Q + (size_t)bh * LL * DHEAD;
    const float* Kg = g_K + (size_t)bh * LL * DHEAD;
    const float* Vg = g_V + (size_t)bh * DHEAD * LL;   // transposed [d][L]
    const int* mg = mask + (size_t)b * LL;

    // Q fragments straight from gmem (once per block)
    uint32_t qa[8][4];
    const int qr = q0 + wid * 16;
    #pragma unroll
    for (int kk = 0; kk < 8; kk++) {
        qa[kk][0] = f2tf(Qg[(size_t)(qr + g) * DHEAD + kk * 8 + tig]);
        qa[kk][1] = f2tf(Qg[(size_t)(qr + g + 8) * DHEAD + kk * 8 + tig]);
        qa[kk][2] = f2tf(Qg[(size_t)(qr + g) * DHEAD + kk * 8 + tig + 4]);
        qa[kk][3] = f2tf(Qg[(size_t)(qr + g + 8) * DHEAD + kk * 8 + tig + 4]);
    }

    float Oacc[8][4];
    #pragma unroll
    for (int j = 0; j < 8; j++)
        #pragma unroll
        for (int r = 0; r < 4; r++) Oacc[j][r] = 0.0f;
    float m_lo = -1e30f, m_hi = -1e30f, l_lo = 0.0f, l_hi = 0.0f;

    for (int k0 = 0; k0 < LL; k0 += 64) {
        __syncthreads();
        // K staging: pair-permute cols within each 8-group
        #pragma unroll
        for (int i = 0; i < 4; i++) {
            int idx = tid + i * 256;
            int r = idx >> 4, c0 = (idx & 15) * 4;
            float4 kv = *(const float4*)(Kg + (size_t)(k0 + r) * DHEAD + c0);
            uint32_t* p = &Ks[r * KP2 + (c0 >> 3) * 8 + ((c0 >> 2) & 1)];
            p[0] = f2tf(kv.x); p[2] = f2tf(kv.y); p[4] = f2tf(kv.z); p[6] = f2tf(kv.w);
        }
        // V staging from transposed gmem: row=d, pair-permute key cols
        #pragma unroll
        for (int i = 0; i < 4; i++) {
            int idx = tid + i * 256;
            int d = idx >> 4, kc0 = (idx & 15) * 4;
            float4 vv = *(const float4*)(Vg + (size_t)d * LL + k0 + kc0);
            uint32_t* p = &Vt[d * KP2 + (kc0 & ~7) + 2 * (kc0 & 3) + ((kc0 >> 2) & 1)];
            p[0] = f2tf(vv.x); p[2] = f2tf(vv.y); p[4] = f2tf(vv.z); p[6] = f2tf(vv.w);
        }
        if (tid < 64) madd[tid] = mg[k0 + tid] ? 0.0f : -1e30f;
        __syncthreads();

        // S = Q @ K^T : LDS.64 B-fragments
        float Sc[8][4];
        #pragma unroll
        for (int j = 0; j < 8; j++)
            #pragma unroll
            for (int r = 0; r < 4; r++) Sc[j][r] = 0.0f;

        #pragma unroll
        for (int kk = 0; kk < 8; kk++) {
            #pragma unroll
            for (int j = 0; j < 8; j++) {
                uint2 bp = *(const uint2*)&Ks[(j * 8 + g) * KP2 + kk * 8 + 2 * tig];
                mma8(Sc[j], qa[kk], (const uint32_t*)&bp);
            }
        }

        // online softmax
        const float scale = 0.125f;
        float rmax_lo = -1e30f, rmax_hi = -1e30f;
        #pragma unroll
        for (int j = 0; j < 8; j++) {
            float ma0 = madd[j * 8 + 2 * tig];
            float ma1 = madd[j * 8 + 2 * tig + 1];
            Sc[j][0] = Sc[j][0] * scale + ma0;
            Sc[j][1] = Sc[j][1] * scale + ma1;
            Sc[j][2] = Sc[j][2] * scale + ma0;
            Sc[j][3] = Sc[j][3] * scale + ma1;
            rmax_lo = fmaxf(rmax_lo, fmaxf(Sc[j][0], Sc[j][1]));
            rmax_hi = fmaxf(rmax_hi, fmaxf(Sc[j][2], Sc[j][3]));
        }
        rmax_lo = fmaxf(rmax_lo, __shfl_xor_sync(0xffffffffu, rmax_lo, 1));
        rmax_lo = fmaxf(rmax_lo, __shfl_xor_sync(0xffffffffu, rmax_lo, 2));
        rmax_hi = fmaxf(rmax_hi, __shfl_xor_sync(0xffffffffu, rmax_hi, 1));
        rmax_hi = fmaxf(rmax_hi, __shfl_xor_sync(0xffffffffu, rmax_hi, 2));

        float mn_lo = fmaxf(m_lo, rmax_lo), mn_hi = fmaxf(m_hi, rmax_hi);
        float al = __expf(m_lo - mn_lo), ah = __expf(m_hi - mn_hi);
        m_lo = mn_lo; m_hi = mn_hi;

        float rs_lo = 0.0f, rs_hi = 0.0f;
        uint32_t pa[8][4];
        #pragma unroll
        for (int j = 0; j < 8; j++) {
            float p0 = __expf(Sc[j][0] - mn_lo);
            float p1 = __expf(Sc[j][1] - mn_lo);
            float p2 = __expf(Sc[j][2] - mn_hi);
            float p3 = __expf(Sc[j][3] - mn_hi);
            rs_lo += p0 + p1;
            rs_hi += p2 + p3;
            // C-layout -> A-layout via shfl
            float t00 = __shfl_sync(0xffffffffu, p0, bl | lo);
            float t01 = __shfl_sync(0xffffffffu, p1, bl | lo);
            float t20 = __shfl_sync(0xffffffffu, p0, bl | lo | 2);
            float t21 = __shfl_sync(0xffffffffu, p1, bl | lo | 2);
            float t10 = __shfl_sync(0xffffffffu, p2, bl | lo);
            float t11 = __shfl_sync(0xffffffffu, p3, bl | lo);
            float t30 = __shfl_sync(0xffffffffu, p2, bl | lo | 2);
            float t31 = __shfl_sync(0xffffffffu, p3, bl | lo | 2);
            pa[j][0] = f2tf(sel ? t01 : t00);
            pa[j][1] = f2tf(sel ? t11 : t10);
            pa[j][2] = f2tf(sel ? t21 : t20);
            pa[j][3] = f2tf(sel ? t31 : t30);
        }
        rs_lo += __shfl_xor_sync(0xffffffffu, rs_lo, 1);
        rs_lo += __shfl_xor_sync(0xffffffffu, rs_lo, 2);
        rs_hi += __shfl_xor_sync(0xffffffffu, rs_hi, 1);
        rs_hi += __shfl_xor_sync(0xffffffffu, rs_hi, 2);

        l_lo = l_lo * al + rs_lo;
        l_hi = l_hi * ah + rs_hi;
        #pragma unroll
        for (int j = 0; j < 8; j++) {
            Oacc[j][0] *= al; Oacc[j][1] *= al;
            Oacc[j][2] *= ah; Oacc[j][3] *= ah;
        }

        // O += P @ V : LDS.64 B-fragments from Vt
        #pragma unroll
        for (int kk = 0; kk < 8; kk++) {
            #pragma unroll
            for (int j = 0; j < 8; j++) {
                uint2 bp = *(const uint2*)&Vt[(j * 8 + g) * KP2 + kk * 8 + 2 * tig];
                mma8(Oacc[j], pa[kk], (const uint32_t*)&bp);
            }
        }
    }

    // epilogue: normalize, write [B, L, H*64]
    float inv_lo = 1.0f / l_lo, inv_hi = 1.0f / l_hi;
    int row_lo = qr + g;
    int row_hi = row_lo + 8;
    #pragma unroll
    for (int j = 0; j < 8; j++) {
        int col = h * DHEAD + j * 8 + 2 * tig;
        *(float2*)&g_O[((size_t)b * LL + row_lo) * DMODEL + col] =
            make_float2(Oacc[j][0] * inv_lo, Oacc[j][1] * inv_lo);
        *(float2*)&g_O[((size_t)b * LL + row_hi) * DMODEL + col] =
            make_float2(Oacc[j][2] * inv_hi, Oacc[j][3] * inv_hi);
    }
}

// ---------------------------------------------------------------------------
extern "C" void kernel_launch(void* const* d_in, const int* in_sizes, int n_in,
                              void* d_out, int out_size)
{
    const float* q    = (const float*)d_in[0];
    const float* k    = (const float*)d_in[1];
    const float* v    = (const float*)d_in[2];
    const int*   mask = (const int*)  d_in[3];
    const float* Wq   = (const float*)d_in[4];
    const float* Wk   = (const float*)d_in[5];
    const float* Wv   = (const float*)d_in[6];
    const float* Wo   = (const float*)d_in[7];
    float* out = (float*)d_out;

    void *pQ, *pK, *pV, *pO;
    cudaGetSymbolAddress(&pQ, g_Q);
    cudaGetSymbolAddress(&pK, g_K);
    cudaGetSymbolAddress(&pV, g_V);
    cudaGetSymbolAddress(&pO, g_O);

    dim3 blk(256);
    dim3 gproj(DMODEL / 128, (BB * LL) / 128);   // (4, 64)

    gemm_tf32<<<gproj, blk>>>(q, Wq, (float*)pQ, 1);
    gemm_tf32<<<gproj, blk>>>(k, Wk, (float*)pK, 1);
    gemm_tf32<<<gproj, blk>>>(v, Wv, (float*)pV, 2);
    attn_tf32<<<dim3(LL / 128, BB * NH), 256>>>(mask);
    gemm_tf32<<<gproj, blk>>>((const float*)pO, Wo, out, 0);
}